// round 6
// baseline (speedup 1.0000x reference)
#include <cuda_runtime.h>

#define N_ZQ   2097152   // 8*64*64*64
#define N_IDX  32768
#define K_ROWS 8192
#define D_DIM  64
#define NB     512
#define NT     256

// Scratch (device globals; no allocation). Ticket counters are monotone:
// 2^32 % NB == 0, so (ret & (NB-1)) == NB-1 detects the last arrival of
// every generation across unlimited graph replays — no resets needed.
__device__ unsigned long long g_amin[NB];
__device__ double g_losspart[NB];
__device__ unsigned int g_tick1, g_tick2;
__device__ int g_kmin;
__device__ float g_bookrow[D_DIM];

// ---------------------------------------------------------------------------
// Kernel 1: book argmin. 512x256 = one float4 per thread covers all
// 8192 rows x 16 float4s. 16 consecutive lanes share a row (shfl butterfly).
// The LAST block to arrive (ticket) reduces the 512 partials and publishes
// g_kmin + the winning 64-float row. Nobody spins.
// ---------------------------------------------------------------------------
__global__ void __launch_bounds__(NT)
k_argmin(const float* __restrict__ book) {
    __shared__ unsigned long long s[NT];
    __shared__ int last;
    int t = threadIdx.x, b = blockIdx.x;

    int f = b * NT + t;                         // book float4 id
    float4 v = reinterpret_cast<const float4*>(book)[f];
    float acc = v.x * v.x;
    acc = fmaf(v.y, v.y, acc);
    acc = fmaf(v.z, v.z, acc);
    acc = fmaf(v.w, v.w, acc);
#pragma unroll
    for (int off = 1; off < 16; off <<= 1)
        acc += __shfl_xor_sync(0xffffffffu, acc, off);
    // positive-float bits monotone: u64-min == (min norm, lowest row index)
    unsigned long long key =
        ((unsigned long long)__float_as_uint(acc) << 32) | (unsigned)(f >> 4);
    s[t] = key;
    __syncthreads();
#pragma unroll
    for (int off = NT / 2; off > 0; off >>= 1) {
        if (t < off) {
            unsigned long long o = s[t + off];
            if (o < s[t]) s[t] = o;
        }
        __syncthreads();
    }
    if (t == 0) {
        g_amin[b] = s[0];
        __threadfence();
        unsigned r = atomicAdd(&g_tick1, 1u);
        last = ((r & (NB - 1)) == NB - 1);
    }
    __syncthreads();
    if (last) {
        volatile unsigned long long* ga = g_amin;
        unsigned long long a = ga[t], c = ga[t + NT];
        s[t] = (c < a) ? c : a;
        __syncthreads();
#pragma unroll
        for (int off = NT / 2; off > 0; off >>= 1) {
            if (t < off) {
                unsigned long long o = s[t + off];
                if (o < s[t]) s[t] = o;
            }
            __syncthreads();
        }
        int kmin = (int)(s[0] & 0xffffffffu);
        if (t < D_DIM) g_bookrow[t] = book[(size_t)kmin * D_DIM + t];
        if (t == 0) g_kmin = kmin;
    }
}

// ---------------------------------------------------------------------------
// Kernel 2: fused streaming + loss. Kernel boundary = sync for g_bookrow.
// stride = NB*NT = 131072 is a multiple of 16 and 1024, so both derived
// indices ((4j)&63 and (j>>10)&63) are identical for all 4 chunks -> hoisted.
// Loop body: 4 independent float4 loads, 16 FMAs, 4 broadcast stores.
// Loss finalized by the last-arriving block (no spin, no 3rd kernel).
// ---------------------------------------------------------------------------
__global__ void __launch_bounds__(NT)
k_main(const float* __restrict__ in, float* __restrict__ out, int out_size) {
    __shared__ float swr[8];
    __shared__ int last;
    int t = threadIdx.x, b = blockIdx.x;

    int kmin = g_kmin;                          // uniform load, L2 (L1 flushed at launch)
    int gtid = b * NT + t;
    const int stride = NB * NT;

    const float4* in4  = reinterpret_cast<const float4*>(in);
    float4*       out4 = reinterpret_cast<float4*>(out);

    // hoisted indices (k-invariant, see note above)
    int w0 = (gtid << 2) & 63;
    float b0 = g_bookrow[w0];
    float b1 = g_bookrow[w0 + 1];
    float b2 = g_bookrow[w0 + 2];
    float b3 = g_bookrow[w0 + 3];
    float vz = g_bookrow[(gtid >> 10) & 63];
    float4 vq = make_float4(vz, vz, vz, vz);

    // front-batched independent loads (MLP=4)
    float4 x0 = in4[gtid];
    float4 x1 = in4[gtid + stride];
    float4 x2 = in4[gtid + 2 * stride];
    float4 x3 = in4[gtid + 3 * stride];

    float lsum = 0.0f;
    float d;
    d = b0 - x0.x; lsum = fmaf(d, d, lsum);
    d = b1 - x0.y; lsum = fmaf(d, d, lsum);
    d = b2 - x0.z; lsum = fmaf(d, d, lsum);
    d = b3 - x0.w; lsum = fmaf(d, d, lsum);
    d = b0 - x1.x; lsum = fmaf(d, d, lsum);
    d = b1 - x1.y; lsum = fmaf(d, d, lsum);
    d = b2 - x1.z; lsum = fmaf(d, d, lsum);
    d = b3 - x1.w; lsum = fmaf(d, d, lsum);
    d = b0 - x2.x; lsum = fmaf(d, d, lsum);
    d = b1 - x2.y; lsum = fmaf(d, d, lsum);
    d = b2 - x2.z; lsum = fmaf(d, d, lsum);
    d = b3 - x2.w; lsum = fmaf(d, d, lsum);
    d = b0 - x3.x; lsum = fmaf(d, d, lsum);
    d = b1 - x3.y; lsum = fmaf(d, d, lsum);
    d = b2 - x3.z; lsum = fmaf(d, d, lsum);
    d = b3 - x3.w; lsum = fmaf(d, d, lsum);

    out4[gtid]              = vq;
    out4[gtid + stride]     = vq;
    out4[gtid + 2 * stride] = vq;
    out4[gtid + 3 * stride] = vq;

    // idx section: constant argmin index as float (first 8192 threads)
    if (out_size >= N_ZQ + N_IDX && gtid < N_IDX / 4) {
        float fk = (float)kmin;
        out4[N_ZQ / 4 + gtid] = make_float4(fk, fk, fk, fk);
    }

    // block loss partial
#pragma unroll
    for (int off = 16; off > 0; off >>= 1)
        lsum += __shfl_down_sync(0xffffffffu, lsum, off);
    if ((t & 31) == 0) swr[t >> 5] = lsum;
    __syncthreads();
    if (t == 0) {
        double ds = 0.0;
#pragma unroll
        for (int i = 0; i < 8; ++i) ds += (double)swr[i];
        g_losspart[b] = ds;
        __threadfence();
        unsigned r = atomicAdd(&g_tick2, 1u);
        last = ((r & (NB - 1)) == NB - 1);
    }
    __syncthreads();
    if (last) {
        __shared__ double sd[NT];
        volatile double* gl = g_losspart;
        sd[t] = gl[t] + gl[t + NT];
        __syncthreads();
#pragma unroll
        for (int off = NT / 2; off > 0; off >>= 1) {
            if (t < off) sd[t] += sd[t + off];
            __syncthreads();
        }
        if (t == 0 && out_size >= N_ZQ + N_IDX + 1)
            out[N_ZQ + N_IDX] = (float)(1.25 * sd[0] / (double)N_ZQ);
    }
}

extern "C" void kernel_launch(void* const* d_in, const int* in_sizes, int n_in,
                              void* d_out, int out_size) {
    const float* input = (const float*)d_in[0];
    const float* book  = (const float*)d_in[1];
    if (n_in >= 2 && in_sizes[0] == K_ROWS * D_DIM && in_sizes[1] == N_ZQ) {
        const float* tmp = input; input = book; book = tmp;
    }
    k_argmin<<<NB, NT>>>(book);
    k_main<<<NB, NT>>>(input, (float*)d_out, out_size);
}

// round 10
// speedup vs baseline: 1.0367x; 1.0367x over previous
#include <cuda_runtime.h>

// R10: third submission of the R8 optimization (R8, R9 both died to broker
// infra failures before running; no kernel-side mechanism can explain them).

#define N_ZQ   2097152   // 8*64*64*64
#define N_IDX  32768
#define K_ROWS 8192
#define D_DIM  64
#define NB1    512       // argmin blocks
#define NB2    1024      // main blocks
#define NT     256

// Device-global scratch (no allocation). Ticket counters are MONOTONE:
// 2^32 % NB == 0 for both NB1 and NB2, so last-arrival detection wraps
// cleanly across unlimited graph replays — no resets, deterministic.
__device__ unsigned long long g_amin[NB1];
__device__ double g_losspart[NB2];
__device__ unsigned int g_tick1, g_tick2;
__device__ int g_kmin;
__device__ float g_bookrow[D_DIM];

// ---------------------------------------------------------------------------
// Kernel 1: book argmin. 512x256: one float4/thread covers 8192 rows x 16
// float4s; 16 consecutive lanes share one row (shfl-xor butterfly). One DRAM
// round trip per thread. Last-arriving block (ticket) reduces the 512
// partials and publishes g_kmin + the winning 64-float row. The launch
// boundary is the consumer-side sync (L1D is flushed at every launch).
// ---------------------------------------------------------------------------
__global__ void __launch_bounds__(NT, 4)
k_argmin(const float* __restrict__ book) {
    __shared__ unsigned long long s[NT];
    __shared__ int last;
    int t = threadIdx.x, b = blockIdx.x;

    int f = b * NT + t;                         // book float4 id
    float4 v = reinterpret_cast<const float4*>(book)[f];
    float acc = v.x * v.x;
    acc = fmaf(v.y, v.y, acc);
    acc = fmaf(v.z, v.z, acc);
    acc = fmaf(v.w, v.w, acc);
#pragma unroll
    for (int off = 1; off < 16; off <<= 1)
        acc += __shfl_xor_sync(0xffffffffu, acc, off);
    // positive-float bit patterns are monotone, so u64-min of
    // (norm_bits<<32)|row == (min norm, lowest row) with tie-break.
    unsigned long long key =
        ((unsigned long long)__float_as_uint(acc) << 32) | (unsigned)(f >> 4);
    s[t] = key;
    __syncthreads();
#pragma unroll
    for (int off = NT / 2; off > 0; off >>= 1) {
        if (t < off) {
            unsigned long long o = s[t + off];
            if (o < s[t]) s[t] = o;
        }
        __syncthreads();
    }
    if (t == 0) {
        g_amin[b] = s[0];
        __threadfence();
        unsigned r = atomicAdd(&g_tick1, 1u);
        last = ((r & (NB1 - 1)) == NB1 - 1);
    }
    __syncthreads();
    if (last) {
        volatile unsigned long long* ga = g_amin;
        unsigned long long a = ga[t], c = ga[t + NT];
        s[t] = (c < a) ? c : a;
        __syncthreads();
#pragma unroll
        for (int off = NT / 2; off > 0; off >>= 1) {
            if (t < off) {
                unsigned long long o = s[t + off];
                if (o < s[t]) s[t] = o;
            }
            __syncthreads();
        }
        int kmin = (int)(s[0] & 0xffffffffu);
        if (t < D_DIM) g_bookrow[t] = book[(size_t)kmin * D_DIM + t];
        if (t == 0) g_kmin = kmin;
    }
}

// ---------------------------------------------------------------------------
// Kernel 2: fused streaming + loss. 1024 blocks x 256 (~6.9 blocks/SM,
// ~55 resident warps/SM), 2 float4s/thread (exact fit, no tail).
// __launch_bounds__(256,4) gives a 64-reg budget so BOTH DRAM float4 loads
// and the 5 L2-hot bookrow loads are front-batched (high MLP). stride =
// 262144 is a multiple of 16 and 1024, so the derived indices (w-slot and
// z_q value slot) are identical across both chunks — hoisted.
// Loss is finalized by the last-arriving block (R6-proven pattern, no spin).
// ---------------------------------------------------------------------------
__global__ void __launch_bounds__(NT, 4)
k_main(const float* __restrict__ in, float* __restrict__ out, int out_size) {
    __shared__ float swr[8];
    __shared__ int last;
    int t = threadIdx.x, b = blockIdx.x;

    int gtid = b * NT + t;
    const int stride = NB2 * NT;               // 262144

    const float4* in4  = reinterpret_cast<const float4*>(in);
    float4*       out4 = reinterpret_cast<float4*>(out);

    // front-batched independent loads
    float4 x0 = in4[gtid];
    float4 x1 = in4[gtid + stride];
    int w0 = (gtid << 2) & 63;
    float b0 = g_bookrow[w0];
    float b1 = g_bookrow[w0 + 1];
    float b2 = g_bookrow[w0 + 2];
    float b3 = g_bookrow[w0 + 3];
    float vz = g_bookrow[(gtid >> 10) & 63];
    int kmin = g_kmin;

    float lsum = 0.0f;
    float d;
    d = b0 - x0.x; lsum = fmaf(d, d, lsum);
    d = b1 - x0.y; lsum = fmaf(d, d, lsum);
    d = b2 - x0.z; lsum = fmaf(d, d, lsum);
    d = b3 - x0.w; lsum = fmaf(d, d, lsum);
    d = b0 - x1.x; lsum = fmaf(d, d, lsum);
    d = b1 - x1.y; lsum = fmaf(d, d, lsum);
    d = b2 - x1.z; lsum = fmaf(d, d, lsum);
    d = b3 - x1.w; lsum = fmaf(d, d, lsum);

    float4 vq = make_float4(vz, vz, vz, vz);
    out4[gtid]          = vq;
    out4[gtid + stride] = vq;

    // idx section: constant argmin index as float (first 8192 threads)
    if (out_size >= N_ZQ + N_IDX && gtid < N_IDX / 4) {
        float fk = (float)kmin;
        out4[N_ZQ / 4 + gtid] = make_float4(fk, fk, fk, fk);
    }

    // block loss partial -> scratch; last-arriving block finalizes
#pragma unroll
    for (int off = 16; off > 0; off >>= 1)
        lsum += __shfl_down_sync(0xffffffffu, lsum, off);
    if ((t & 31) == 0) swr[t >> 5] = lsum;
    __syncthreads();
    if (t == 0) {
        double ds = 0.0;
#pragma unroll
        for (int i = 0; i < 8; ++i) ds += (double)swr[i];
        g_losspart[b] = ds;
        __threadfence();
        unsigned r = atomicAdd(&g_tick2, 1u);
        last = ((r & (NB2 - 1)) == NB2 - 1);
    }
    __syncthreads();
    if (last) {
        __shared__ double sd[NT];
        volatile double* gl = g_losspart;
        double acc2 = 0.0;
#pragma unroll
        for (int i = 0; i < NB2 / NT; ++i) acc2 += gl[t + i * NT];
        sd[t] = acc2;
        __syncthreads();
#pragma unroll
        for (int off = NT / 2; off > 0; off >>= 1) {
            if (t < off) sd[t] += sd[t + off];
            __syncthreads();
        }
        if (t == 0 && out_size >= N_ZQ + N_IDX + 1)
            out[N_ZQ + N_IDX] = (float)(1.25 * sd[0] / (double)N_ZQ);
    }
}

extern "C" void kernel_launch(void* const* d_in, const int* in_sizes, int n_in,
                              void* d_out, int out_size) {
    const float* input = (const float*)d_in[0];
    const float* book  = (const float*)d_in[1];
    if (n_in >= 2 && in_sizes[0] == K_ROWS * D_DIM && in_sizes[1] == N_ZQ) {
        const float* tmp = input; input = book; book = tmp;
    }
    k_argmin<<<NB1, NT>>>(book);
    k_main<<<NB2, NT>>>(input, (float*)d_out, out_size);
}